// round 2
// baseline (speedup 1.0000x reference)
#include <cuda_runtime.h>
#include <math.h>

// Problem dims
#define NB   8
#define LB   4096
#define HB   1024
#define KB   1024
#define MTOT (NB * LB)      // 32768 rows of x
#define SEG    32
#define SEGLEN (LB / SEG)   // 128

// GEMM tiling
#define BM 128
#define BN 64   // o' pairs per block (covers W rows o' and o'+1024)
#define BK 16

// Scratch (no cudaMalloc allowed): a = sigmoid(-z), v = sigmoid(z)*g(h_inter)
__device__ float g_a[(size_t)MTOT * HB];   // 128 MB
__device__ float g_v[(size_t)MTOT * HB];   // 128 MB
__device__ float g_Aseg[NB * SEG * HB];
__device__ float g_Bseg[NB * SEG * HB];
__device__ float g_Cin [NB * SEG * HB];

// ---------------------------------------------------------------------------
// Kernel 1: fp32 GEMM  zh = x * W^T + b, fused epilogue -> (a, v)
// Block computes BM x BN "pairs": for each (m, o') both z (W row o') and
// h_inter (W row o'+1024).
// ---------------------------------------------------------------------------
__global__ void __launch_bounds__(256, 2)
gemm_av_kernel(const float* __restrict__ x,
               const float* __restrict__ W,
               const float* __restrict__ b)
{
    __shared__ float As[BK][BM + 4];        // [k][m]
    __shared__ float Bs[BK][2 * BN + 4];    // [k][row], rows 0..63 = z, 64..127 = h_inter

    const int tid = threadIdx.x;
    const int tx  = tid & 15;   // o' group (4 per thread)
    const int ty  = tid >> 4;   // m group  (8 per thread)
    const int m0  = blockIdx.y * BM;
    const int o0  = blockIdx.x * BN;

    float acc[8][4][2];
    #pragma unroll
    for (int i = 0; i < 8; i++)
        #pragma unroll
        for (int j = 0; j < 4; j++) { acc[i][j][0] = 0.f; acc[i][j][1] = 0.f; }

    const float* xblk = x + (size_t)m0 * KB;

    for (int kt = 0; kt < KB; kt += BK) {
        // Load A tile: 128x16 floats = 512 float4, 2 per thread
        #pragma unroll
        for (int r = 0; r < 2; r++) {
            int f  = tid + r * 256;      // float4 index
            int m  = f >> 2;
            int k4 = (f & 3) * 4;
            float4 val = *(const float4*)(&xblk[(size_t)m * KB + kt + k4]);
            As[k4 + 0][m] = val.x; As[k4 + 1][m] = val.y;
            As[k4 + 2][m] = val.z; As[k4 + 3][m] = val.w;
        }
        // Load B tile: rows 0..63 -> W[o0+row], rows 64..127 -> W[o0+row-64+HB]
        #pragma unroll
        for (int r = 0; r < 2; r++) {
            int f   = tid + r * 256;
            int row = f >> 2;
            int k4  = (f & 3) * 4;
            int wrow = (row < BN) ? (o0 + row) : (o0 + row - BN + HB);
            float4 val = *(const float4*)(&W[(size_t)wrow * KB + kt + k4]);
            Bs[k4 + 0][row] = val.x; Bs[k4 + 1][row] = val.y;
            Bs[k4 + 2][row] = val.z; Bs[k4 + 3][row] = val.w;
        }
        __syncthreads();

        #pragma unroll
        for (int k = 0; k < BK; k++) {
            float ra[8], rbz[4], rbh[4];
            #pragma unroll
            for (int i = 0; i < 8; i++) ra[i] = As[k][ty * 8 + i];
            #pragma unroll
            for (int j = 0; j < 4; j++) {
                rbz[j] = Bs[k][tx * 4 + j];
                rbh[j] = Bs[k][BN + tx * 4 + j];
            }
            #pragma unroll
            for (int i = 0; i < 8; i++)
                #pragma unroll
                for (int j = 0; j < 4; j++) {
                    acc[i][j][0] = fmaf(ra[i], rbz[j], acc[i][j][0]);
                    acc[i][j][1] = fmaf(ra[i], rbh[j], acc[i][j][1]);
                }
        }
        __syncthreads();
    }

    // Epilogue: a = sigmoid(-z), v = sigmoid(z) * g(h_inter)
    #pragma unroll
    for (int i = 0; i < 8; i++) {
        int m = m0 + ty * 8 + i;
        float4 av, vv;
        float* avp = (float*)&av;
        float* vvp = (float*)&vv;
        #pragma unroll
        for (int j = 0; j < 4; j++) {
            int o = o0 + tx * 4 + j;
            float z  = acc[i][j][0] + b[o];
            float hi = acc[i][j][1] + b[o + HB];
            // stable sigmoid pair
            float t   = expf(-fabsf(z));
            float inv = 1.0f / (1.0f + t);
            float sig = (z >= 0.f) ? inv : t * inv;   // sigmoid(z)
            float a   = (z >= 0.f) ? t * inv : inv;   // sigmoid(-z)
            float gt;
            if (hi >= 0.f) gt = hi + 0.5f;
            else { float t2 = expf(hi); gt = t2 / (1.f + t2); }
            avp[j] = a;
            vvp[j] = sig * gt;
        }
        size_t base = (size_t)m * HB + o0 + tx * 4;
        *(float4*)&g_a[base] = av;
        *(float4*)&g_v[base] = vv;
    }
}

// ---------------------------------------------------------------------------
// Kernel 2: per-segment affine composition: (A, B) s.t. h_out = A*h_in + B
// ---------------------------------------------------------------------------
__global__ void __launch_bounds__(256)
scan_pass1(void)
{
    int h   = blockIdx.x * 256 + threadIdx.x;
    int seg = blockIdx.y;
    int n   = blockIdx.z;
    size_t base = ((size_t)(n * LB + seg * SEGLEN)) * HB + h;

    float A = 1.f, B = 0.f;
    #pragma unroll 4
    for (int i = 0; i < SEGLEN; i++) {
        float a = g_a[base + (size_t)i * HB];
        float v = g_v[base + (size_t)i * HB];
        B = fmaf(a, B, v);
        A *= a;
    }
    int idx = (n * SEG + seg) * HB + h;
    g_Aseg[idx] = A;
    g_Bseg[idx] = B;
}

// ---------------------------------------------------------------------------
// Kernel 3: sequential scan over the SEG segment summaries per (n, h)
// ---------------------------------------------------------------------------
__global__ void __launch_bounds__(256)
scan_pass2(const float* __restrict__ hx)
{
    int h = blockIdx.x * 256 + threadIdx.x;
    int n = blockIdx.y;
    float hcur = hx[n * HB + h];
    for (int s = 0; s < SEG; s++) {
        int idx = (n * SEG + s) * HB + h;
        g_Cin[idx] = hcur;
        hcur = fmaf(g_Aseg[idx], hcur, g_Bseg[idx]);
    }
}

// ---------------------------------------------------------------------------
// Kernel 4: re-scan each segment from its carry-in, writing all outputs
// ---------------------------------------------------------------------------
__global__ void __launch_bounds__(256)
scan_pass3(float* __restrict__ out)
{
    int h   = blockIdx.x * 256 + threadIdx.x;
    int seg = blockIdx.y;
    int n   = blockIdx.z;
    size_t base = ((size_t)(n * LB + seg * SEGLEN)) * HB + h;

    float hcur = g_Cin[(n * SEG + seg) * HB + h];
    #pragma unroll 4
    for (int i = 0; i < SEGLEN; i++) {
        float a = g_a[base + (size_t)i * HB];
        float v = g_v[base + (size_t)i * HB];
        hcur = fmaf(a, hcur, v);
        out[base + (size_t)i * HB] = hcur;
    }
}

// ---------------------------------------------------------------------------
extern "C" void kernel_launch(void* const* d_in, const int* in_sizes, int n_in,
                              void* d_out, int out_size)
{
    const float *x = nullptr, *W = nullptr, *b = nullptr, *hx = nullptr;
    for (int i = 0; i < n_in; i++) {
        switch (in_sizes[i]) {
            case 33554432: x  = (const float*)d_in[i]; break;
            case 2097152:  W  = (const float*)d_in[i]; break;
            case 2048:     b  = (const float*)d_in[i]; break;
            case 8192:     hx = (const float*)d_in[i]; break;
        }
    }
    float* out = (float*)d_out;

    dim3 gemm_grid(HB / BN, MTOT / BM);   // (16, 256)
    gemm_av_kernel<<<gemm_grid, 256>>>(x, W, b);

    scan_pass1<<<dim3(HB / 256, SEG, NB), 256>>>();
    scan_pass2<<<dim3(HB / 256, NB), 256>>>(hx);
    scan_pass3<<<dim3(HB / 256, SEG, NB), 256>>>(out);
}

// round 4
// speedup vs baseline: 1.8158x; 1.8158x over previous
#include <cuda_runtime.h>
#include <cuda_bf16.h>
#include <cstdint>
#include <math.h>

// ---------------- problem dims ----------------
#define NB   8
#define LB   4096
#define HB   1024
#define KB   1024
#define MTOT (NB * LB)          // 32768
#define SEG    32
#define SEGLEN (LB / SEG)       // 128

// ---------------- GEMM tiling -----------------
#define BM 128                  // M rows / CTA
#define BNP 64                  // o-pairs / CTA  (B tile = 128 interleaved rows)
#define BK 32                   // K elems per stage
#define NKT (KB / BK)           // 32
#define PIPE 4

// per-stage smem layout (bytes): each tile 128 rows x 64B
#define T_AHI 0
#define T_ALO 8192
#define T_BHI 16384
#define T_BLO 24576
#define STAGE_BYTES 32768
#define SMEM_DYN (PIPE * STAGE_BYTES)

// ---------------- device scratch ----------------
__device__ float g_a[(size_t)MTOT * HB];   // sigmoid(-z)
__device__ float g_v[(size_t)MTOT * HB];   // sigmoid(z)*g(h_inter)
__device__ float g_Aseg[NB * SEG * HB];
__device__ float g_Bseg[NB * SEG * HB];
__device__ float g_Cin [NB * SEG * HB];
__device__ __nv_bfloat16 g_xhi[(size_t)MTOT * KB];
__device__ __nv_bfloat16 g_xlo[(size_t)MTOT * KB];
__device__ __nv_bfloat16 g_whi[(size_t)2 * HB * KB];
__device__ __nv_bfloat16 g_wlo[(size_t)2 * HB * KB];

// ---------------- helpers ----------------
__device__ __forceinline__ uint32_t smem_u32(const void* p) {
    uint32_t a;
    asm("{ .reg .u64 t; cvta.to.shared.u64 t, %1; cvt.u32.u64 %0, t; }" : "=r"(a) : "l"(p));
    return a;
}
// tile byte offset with XOR swizzle: row*64 + (chunk ^ ((row>>1)&3))*16
__device__ __forceinline__ uint32_t swz(int row, int chunk) {
    return (uint32_t)(row * 64 + ((chunk ^ ((row >> 1) & 3)) << 4));
}
#define CP_ASYNC16(sdst, gsrc) \
    asm volatile("cp.async.cg.shared.global [%0], [%1], 16;" :: "r"(sdst), "l"(gsrc))
#define CP_COMMIT() asm volatile("cp.async.commit_group;" ::: "memory")
#define CP_WAIT2()  asm volatile("cp.async.wait_group 2;" ::: "memory")
#define CP_WAIT0()  asm volatile("cp.async.wait_group 0;" ::: "memory")

__device__ __forceinline__ void ldmx4(uint32_t* r, uint32_t addr) {
    asm volatile("ldmatrix.sync.aligned.m8n8.x4.shared.b16 {%0,%1,%2,%3}, [%4];"
        : "=r"(r[0]), "=r"(r[1]), "=r"(r[2]), "=r"(r[3]) : "r"(addr));
}
__device__ __forceinline__ void mma16816(float* c, const uint32_t* a, uint32_t b0, uint32_t b1) {
    asm volatile("mma.sync.aligned.m16n8k16.row.col.f32.bf16.bf16.f32 "
        "{%0,%1,%2,%3}, {%4,%5,%6,%7}, {%8,%9}, {%0,%1,%2,%3};"
        : "+f"(c[0]), "+f"(c[1]), "+f"(c[2]), "+f"(c[3])
        : "r"(a[0]), "r"(a[1]), "r"(a[2]), "r"(a[3]), "r"(b0), "r"(b1));
}

// ---------------------------------------------------------------------------
// Split fp32 -> bf16 hi + lo
// ---------------------------------------------------------------------------
__global__ void __launch_bounds__(256)
split_x_kernel(const float* __restrict__ src)
{
    size_t i = (size_t)blockIdx.x * 256 + threadIdx.x;   // float4 index
    float4 v = ((const float4*)src)[i];
    float f[4] = {v.x, v.y, v.z, v.w};
    __nv_bfloat16 h[4], l[4];
    #pragma unroll
    for (int j = 0; j < 4; j++) {
        h[j] = __float2bfloat16(f[j]);
        l[j] = __float2bfloat16(f[j] - __bfloat162float(h[j]));
    }
    *(uint2*)&g_xhi[i * 4] = *(uint2*)h;
    *(uint2*)&g_xlo[i * 4] = *(uint2*)l;
}
__global__ void __launch_bounds__(256)
split_w_kernel(const float* __restrict__ src)
{
    size_t i = (size_t)blockIdx.x * 256 + threadIdx.x;
    float4 v = ((const float4*)src)[i];
    float f[4] = {v.x, v.y, v.z, v.w};
    __nv_bfloat16 h[4], l[4];
    #pragma unroll
    for (int j = 0; j < 4; j++) {
        h[j] = __float2bfloat16(f[j]);
        l[j] = __float2bfloat16(f[j] - __bfloat162float(h[j]));
    }
    *(uint2*)&g_whi[i * 4] = *(uint2*)h;
    *(uint2*)&g_wlo[i * 4] = *(uint2*)l;
}

// ---------------------------------------------------------------------------
// bf16-split tensor-core GEMM (mma.sync) with fused (a, v) epilogue.
// B tile rows interleave z / h_inter: row j -> W[o0p + (j>>1) + (j&1)*HB].
// ---------------------------------------------------------------------------
__global__ void __launch_bounds__(256)
gemm_mma_kernel(const float* __restrict__ b)
{
    extern __shared__ char dynsmem[];
    const uint32_t sbase = smem_u32(dynsmem);

    const int tid = threadIdx.x;
    const int wid = tid >> 5;
    const int l   = tid & 31;
    const int wm  = wid & 3;          // warp m index: rows wm*32 .. +31
    const int wn  = wid >> 2;         // warp n index: cols wn*64 .. +63
    const int m0  = blockIdx.y * BM;
    const int o0p = blockIdx.x * BNP; // o-pair base

    // global source pointers for this thread's cp.async slots
    // each thread loads 2 (row,chunk) entries per tile: e = tid*2 + i
    int rowA[2], chA[2];
    const __nv_bfloat16 *srcAh[2], *srcAl[2], *srcBh[2], *srcBl[2];
    uint32_t dA[2], dB[2];
    #pragma unroll
    for (int i = 0; i < 2; i++) {
        int e = tid * 2 + i;
        int row = e >> 2, ch = e & 3;
        rowA[i] = row; chA[i] = ch;
        srcAh[i] = g_xhi + (size_t)(m0 + row) * KB + ch * 8;
        srcAl[i] = g_xlo + (size_t)(m0 + row) * KB + ch * 8;
        int wrow = (row & 1) ? (HB + o0p + (row >> 1)) : (o0p + (row >> 1));
        srcBh[i] = g_whi + (size_t)wrow * KB + ch * 8;
        srcBl[i] = g_wlo + (size_t)wrow * KB + ch * 8;
        dA[i] = swz(row, ch);
        dB[i] = swz(row, ch);
    }

    float acc[2][8][4];
    #pragma unroll
    for (int a0 = 0; a0 < 2; a0++)
        #pragma unroll
        for (int a1 = 0; a1 < 8; a1++)
            #pragma unroll
            for (int a2 = 0; a2 < 4; a2++) acc[a0][a1][a2] = 0.f;

    // prologue: fill PIPE-1 stages
    #pragma unroll
    for (int s = 0; s < PIPE - 1; s++) {
        uint32_t st = sbase + s * STAGE_BYTES;
        int kt = s * BK;
        #pragma unroll
        for (int i = 0; i < 2; i++) {
            CP_ASYNC16(st + T_AHI + dA[i], srcAh[i] + kt);
            CP_ASYNC16(st + T_ALO + dA[i], srcAl[i] + kt);
            CP_ASYNC16(st + T_BHI + dB[i], srcBh[i] + kt);
            CP_ASYNC16(st + T_BLO + dB[i], srcBl[i] + kt);
        }
        CP_COMMIT();
    }

    // per-lane ldmatrix row components
    const int lrow  = l & 15;
    const int lchnk = l >> 4;        // 0/1 -> k8 half

    for (int kt = 0; kt < NKT; kt++) {
        CP_WAIT2();
        __syncthreads();

        const uint32_t st = sbase + (kt % PIPE) * STAGE_BYTES;
        #pragma unroll
        for (int s = 0; s < 2; s++) {           // two k16 steps per stage
            uint32_t ah[2][4], al[2][4], bh[4][4], bl[4][4];
            #pragma unroll
            for (int mt = 0; mt < 2; mt++) {
                int row = wm * 32 + mt * 16 + lrow;
                uint32_t off = swz(row, 2 * s + lchnk);
                ldmx4(ah[mt], st + T_AHI + off);
                ldmx4(al[mt], st + T_ALO + off);
            }
            #pragma unroll
            for (int nt = 0; nt < 4; nt++) {
                int row = wn * 64 + nt * 16 + lrow;
                uint32_t off = swz(row, 2 * s + lchnk);
                ldmx4(bh[nt], st + T_BHI + off);
                ldmx4(bl[nt], st + T_BLO + off);
            }
            #pragma unroll
            for (int mt = 0; mt < 2; mt++)
                #pragma unroll
                for (int nt = 0; nt < 4; nt++) {
                    mma16816(acc[mt][nt * 2],     ah[mt], bh[nt][0], bh[nt][2]);
                    mma16816(acc[mt][nt * 2 + 1], ah[mt], bh[nt][1], bh[nt][3]);
                    mma16816(acc[mt][nt * 2],     ah[mt], bl[nt][0], bl[nt][2]);
                    mma16816(acc[mt][nt * 2 + 1], ah[mt], bl[nt][1], bl[nt][3]);
                    mma16816(acc[mt][nt * 2],     al[mt], bh[nt][0], bh[nt][2]);
                    mma16816(acc[mt][nt * 2 + 1], al[mt], bh[nt][1], bh[nt][3]);
                }
        }
        __syncthreads();

        int ktn = kt + PIPE - 1;
        if (ktn < NKT) {
            uint32_t stl = sbase + (ktn % PIPE) * STAGE_BYTES;
            int ko = ktn * BK;
            #pragma unroll
            for (int i = 0; i < 2; i++) {
                CP_ASYNC16(stl + T_AHI + dA[i], srcAh[i] + ko);
                CP_ASYNC16(stl + T_ALO + dA[i], srcAl[i] + ko);
                CP_ASYNC16(stl + T_BHI + dB[i], srcBh[i] + ko);
                CP_ASYNC16(stl + T_BLO + dB[i], srcBl[i] + ko);
            }
        }
        CP_COMMIT();
    }
    CP_WAIT0();

    // ------------- epilogue: c0 = z, c1 = h_inter (adjacent interleaved cols)
    #pragma unroll
    for (int mt = 0; mt < 2; mt++) {
        #pragma unroll
        for (int nt8 = 0; nt8 < 8; nt8++) {
            int o = o0p + wn * 32 + nt8 * 4 + (l & 3);
            float bz = __ldg(b + o);
            float bh_ = __ldg(b + HB + o);
            #pragma unroll
            for (int half = 0; half < 2; half++) {
                int m = m0 + wm * 32 + mt * 16 + (l >> 2) + half * 8;
                float z  = acc[mt][nt8][half * 2]     + bz;
                float hi = acc[mt][nt8][half * 2 + 1] + bh_;
                float t   = __expf(-fabsf(z));
                float inv = 1.0f / (1.0f + t);
                float sig = (z >= 0.f) ? inv : t * inv;   // sigmoid(z)
                float a   = (z >= 0.f) ? t * inv : inv;   // sigmoid(-z)
                float gt;
                if (hi >= 0.f) gt = hi + 0.5f;
                else { float t2 = __expf(hi); gt = t2 / (1.f + t2); }
                size_t idx = (size_t)m * HB + o;
                g_a[idx] = a;
                g_v[idx] = sig * gt;
            }
        }
    }
}

// ---------------------------------------------------------------------------
// Scan passes
// ---------------------------------------------------------------------------
__global__ void __launch_bounds__(256)
scan_pass1(void)
{
    int h   = blockIdx.x * 256 + threadIdx.x;
    int seg = blockIdx.y;
    int n   = blockIdx.z;
    size_t base = ((size_t)(n * LB + seg * SEGLEN)) * HB + h;
    float A = 1.f, B = 0.f;
    #pragma unroll 4
    for (int i = 0; i < SEGLEN; i++) {
        float a = g_a[base + (size_t)i * HB];
        float v = g_v[base + (size_t)i * HB];
        B = fmaf(a, B, v);
        A *= a;
    }
    int idx = (n * SEG + seg) * HB + h;
    g_Aseg[idx] = A;
    g_Bseg[idx] = B;
}

__global__ void __launch_bounds__(256)
scan_pass2(const float* __restrict__ hx)
{
    int h = blockIdx.x * 256 + threadIdx.x;
    int n = blockIdx.y;
    float hcur = hx[n * HB + h];
    for (int s = 0; s < SEG; s++) {
        int idx = (n * SEG + s) * HB + h;
        g_Cin[idx] = hcur;
        hcur = fmaf(g_Aseg[idx], hcur, g_Bseg[idx]);
    }
}

__global__ void __launch_bounds__(256)
scan_pass3(float* __restrict__ out)
{
    int h   = blockIdx.x * 256 + threadIdx.x;
    int seg = blockIdx.y;
    int n   = blockIdx.z;
    size_t base = ((size_t)(n * LB + seg * SEGLEN)) * HB + h;
    float hcur = g_Cin[(n * SEG + seg) * HB + h];
    #pragma unroll 4
    for (int i = 0; i < SEGLEN; i++) {
        float a = g_a[base + (size_t)i * HB];
        float v = g_v[base + (size_t)i * HB];
        hcur = fmaf(a, hcur, v);
        out[base + (size_t)i * HB] = hcur;
    }
}

// ---------------------------------------------------------------------------
extern "C" void kernel_launch(void* const* d_in, const int* in_sizes, int n_in,
                              void* d_out, int out_size)
{
    const float *x = nullptr, *W = nullptr, *b = nullptr, *hx = nullptr;
    for (int i = 0; i < n_in; i++) {
        switch (in_sizes[i]) {
            case 33554432: x  = (const float*)d_in[i]; break;
            case 2097152:  W  = (const float*)d_in[i]; break;
            case 2048:     b  = (const float*)d_in[i]; break;
            case 8192:     hx = (const float*)d_in[i]; break;
        }
    }
    float* out = (float*)d_out;

    cudaFuncSetAttribute(gemm_mma_kernel, cudaFuncAttributeMaxDynamicSharedMemorySize, SMEM_DYN);

    split_x_kernel<<<(size_t)MTOT * KB / 4 / 256, 256>>>(x);
    split_w_kernel<<<(size_t)2 * HB * KB / 4 / 256, 256>>>(W);

    dim3 gemm_grid(HB / BNP, MTOT / BM);   // (16, 256)
    gemm_mma_kernel<<<gemm_grid, 256, SMEM_DYN>>>(b);

    scan_pass1<<<dim3(HB / 256, SEG, NB), 256>>>();
    scan_pass2<<<dim3(HB / 256, NB), 256>>>(hx);
    scan_pass3<<<dim3(HB / 256, SEG, NB), 256>>>(out);
}